// round 16
// baseline (speedup 1.0000x reference)
#include <cuda_runtime.h>
#include <cuda_bf16.h>
#include <math.h>

#define VOCAB 50000
#define D 256
#define Bn 128
#define Sn 64
#define Ln 32
#define Kn 32

// Scratch (device globals: allocation-free rule)
__device__ float  g_enc [Bn * Sn * D];          // enc_sents   (B,S,D)
__device__ float  g_encW[Bn * Sn * D];          // enc_sents@W (B,S,D)
__device__ float  g_keysV[Bn * Kn * D];         // keys@V      (B,K,D)
__device__ float  g_eK  [Bn * Sn * Kn];         // enc·keys    (B,S,K)
__device__ float2 g_Upk [(D / 2) * D];          // packed U: [p][c]=(U[2p][c],U[2p+1][c])
__device__ float2 g_Wpk [(D / 2) * D];          // packed W
__device__ float2 g_Vpk [(D / 2) * D];          // packed V

#define FMA_F32X2(d_, a_, b_, c_) \
    asm("fma.rn.f32x2 %0, %1, %2, %3;" : "=l"(d_) : "l"(a_), "l"(b_), "l"(c_))

// ---------------------------------------------------------------------------
// Fused: enc_sents[b,s,d] = sum_l emb[prgrph[b,s,l], d]
//        eK[b,s,k]        = sum_d enc[b,s,d] * keys[b,k,d]
// ---------------------------------------------------------------------------
__global__ void gather_eK_kernel(const int* __restrict__ prgrph,
                                 const float* __restrict__ emb,
                                 const float* __restrict__ keys) {
    __shared__ int   sidx[Ln];
    __shared__ float e_sh[D];
    int bs = blockIdx.x;
    int b  = bs / Sn;
    int t  = threadIdx.x;
    int w  = t >> 5, lane = t & 31;
    if (t < Ln) sidx[t] = prgrph[(size_t)bs * Ln + t];
    __syncthreads();
    float acc = 0.f;
#pragma unroll
    for (int l = 0; l < Ln; ++l) acc += __ldg(emb + (size_t)sidx[l] * D + t);
    g_enc[(size_t)bs * D + t] = acc;
    e_sh[t] = acc;
    __syncthreads();
#pragma unroll
    for (int r = 0; r < 4; ++r) {
        int k = w * 4 + r;
        const float* kr = keys + ((size_t)b * Kn + k) * D;
        float p = 0.f;
#pragma unroll
        for (int j = 0; j < 8; ++j) {
            int c = lane + 32 * j;
            p = fmaf(e_sh[c], __ldg(kr + c), p);
        }
#pragma unroll
        for (int o = 16; o > 0; o >>= 1) p += __shfl_xor_sync(0xffffffffu, p, o);
        if (lane == 0) g_eK[(size_t)bs * Kn + k] = p;
    }
}

// ---------------------------------------------------------------------------
// Pack U, W, V into float2 d-pairs: dst[p*D + c] = (M[2p][c], M[2p+1][c])
// ---------------------------------------------------------------------------
__global__ void pack_kernel(const float* __restrict__ U,
                            const float* __restrict__ W,
                            const float* __restrict__ V) {
    int p     = blockIdx.x & 127;
    int which = blockIdx.x >> 7;
    int c     = threadIdx.x;
    const float* M = (which == 0) ? U : (which == 1) ? W : V;
    float2* dst    = (which == 0) ? g_Upk : (which == 1) ? g_Wpk : g_Vpk;
    dst[p * D + c] = make_float2(M[(2 * p) * D + c], M[(2 * p + 1) * D + c]);
}

// ---------------------------------------------------------------------------
// 16-row GEMM tile in scan style: C[16,D] = A[16,D] @ B[D,D] (B packed f32x2)
// warp w lane l: colpair cp = 16w + (l&15), interleaved d-split lh = l>>4:
// lane-half lh covers pairs {g*16 + lh*8 + j}, same 128B line as partner.
// ---------------------------------------------------------------------------
__device__ __forceinline__ void gemm16_f32x2(const float* __restrict__ Ab,
                                             const float2* __restrict__ Bpk,
                                             float* __restrict__ Cb) {
    __shared__ float a_sh[16 * D];
    const int t    = threadIdx.x;
    const int w    = t >> 5;
    const int lane = t & 31;
    const int lh   = lane >> 4;
    const int ll   = lane & 15;
    const int cp   = w * 16 + ll;
    const int c0   = cp * 2;
    const int rb   = lh * 8;

    for (int i = t; i < 16 * D; i += 256) a_sh[i] = Ab[i];
    __syncthreads();

    unsigned long long accA[16], accB[16];
#pragma unroll
    for (int r = 0; r < 16; ++r) { accA[r] = 0ull; accB[r] = 0ull; }

    const ulonglong2* B2 = (const ulonglong2*)Bpk;
#pragma unroll
    for (int g8 = 0; g8 < 8; ++g8) {
        const int p0 = g8 * 16 + lh * 8;   // interleaved d-split
        ulonglong2 u0 = __ldg(B2 + (size_t)(p0 + 0) * 128 + cp);
        ulonglong2 u1 = __ldg(B2 + (size_t)(p0 + 1) * 128 + cp);
        ulonglong2 u2 = __ldg(B2 + (size_t)(p0 + 2) * 128 + cp);
        ulonglong2 u3 = __ldg(B2 + (size_t)(p0 + 3) * 128 + cp);
        ulonglong2 u4 = __ldg(B2 + (size_t)(p0 + 4) * 128 + cp);
        ulonglong2 u5 = __ldg(B2 + (size_t)(p0 + 5) * 128 + cp);
        ulonglong2 u6 = __ldg(B2 + (size_t)(p0 + 6) * 128 + cp);
        ulonglong2 u7 = __ldg(B2 + (size_t)(p0 + 7) * 128 + cp);
#pragma unroll
        for (int r = 0; r < 16; ++r) {
            const ulonglong2* hp = (const ulonglong2*)&a_sh[r * D + p0 * 2];
            ulonglong2 h0 = hp[0], h1 = hp[1], h2 = hp[2], h3 = hp[3];
            FMA_F32X2(accA[r], h0.x, u0.x, accA[r]);
            FMA_F32X2(accB[r], h0.x, u0.y, accB[r]);
            FMA_F32X2(accA[r], h0.y, u1.x, accA[r]);
            FMA_F32X2(accB[r], h0.y, u1.y, accB[r]);
            FMA_F32X2(accA[r], h1.x, u2.x, accA[r]);
            FMA_F32X2(accB[r], h1.x, u2.y, accB[r]);
            FMA_F32X2(accA[r], h1.y, u3.x, accA[r]);
            FMA_F32X2(accB[r], h1.y, u3.y, accB[r]);
            FMA_F32X2(accA[r], h2.x, u4.x, accA[r]);
            FMA_F32X2(accB[r], h2.x, u4.y, accB[r]);
            FMA_F32X2(accA[r], h2.y, u5.x, accA[r]);
            FMA_F32X2(accB[r], h2.y, u5.y, accB[r]);
            FMA_F32X2(accA[r], h3.x, u6.x, accA[r]);
            FMA_F32X2(accB[r], h3.x, u6.y, accB[r]);
            FMA_F32X2(accA[r], h3.y, u7.x, accA[r]);
            FMA_F32X2(accB[r], h3.y, u7.y, accB[r]);
        }
    }

    float sA[16], sB[16];
#pragma unroll
    for (int r = 0; r < 16; ++r) {
        float2 aA = *(float2*)&accA[r];
        float2 aB = *(float2*)&accB[r];
        sA[r] = aA.x + aA.y;
        sB[r] = aB.x + aB.y;
    }
#pragma unroll
    for (int j = 0; j < 8; ++j) {
        float keepA = lh ? sA[8 + j] : sA[j];
        float sendA = lh ? sA[j]     : sA[8 + j];
        float keepB = lh ? sB[8 + j] : sB[j];
        float sendB = lh ? sB[j]     : sB[8 + j];
        float mA = keepA + __shfl_xor_sync(0xffffffffu, sendA, 16);
        float mB = keepB + __shfl_xor_sync(0xffffffffu, sendB, 16);
        *(float2*)&Cb[(rb + j) * D + c0] = make_float2(mA, mB);
    }
}

// encW tiles (0..511) + keysV tiles (512..767)
__global__ void gemm_pre_kernel(const float* __restrict__ keys) {
    int blk = blockIdx.x;
    if (blk < 512) {
        size_t off = (size_t)blk * 16 * D;
        gemm16_f32x2(g_enc + off, g_Wpk, g_encW + off);
    } else {
        size_t off = (size_t)(blk - 512) * 16 * D;
        gemm16_f32x2(keys + off, g_Vpk, g_keysV + off);
    }
}

// ---------------------------------------------------------------------------
// The scan. 256 CTAs = (batch, 16-row half). 256 threads, 2 CTAs/SM.
// Warp w lane l: colpair cp = 16w + (l&15); INTERLEAVED d-split lh = l>>4:
// lane-half lh covers pairs {g*16 + lh*8 + j} so both halves' h broadcasts
// hit the SAME 128B line -> 1 L1 wavefront per LDS (halves crossbar traffic).
// Single __syncthreads per step (h + np/gd double-buffered, rs/gate
// replicated per warp with __syncwarp ordering).
// Partner-swap combine via shfl_xor(16). h UNNORMALIZED; rs folded in.
// ---------------------------------------------------------------------------
#define KH 16

__global__ void __launch_bounds__(256, 2)
scan_kernel(const int* __restrict__ pmask,
            float* __restrict__ out) {
    __shared__ float h[2][KH * D];        // 2 x 16 KB, unnormalized local rows
    __shared__ float np_sh[2][KH * 8];
    __shared__ float gd_sh[2][KH * 8];
    __shared__ float rs_sh[KH];           // benign-race (identical values)
    __shared__ float gate_sh[KH];
    __shared__ int   nxt[Sn + 1];

    const int b    = blockIdx.x >> 1;
    const int half = blockIdx.x & 1;
    const int kgbl = half * KH;
    const int t    = threadIdx.x;
    const int w    = t >> 5;
    const int lane = t & 31;
    const int lh   = lane >> 4;
    const int ll   = lane & 15;
    const int cp   = w * 16 + ll;
    const int c0   = cp * 2;
    const int rb   = lh * 8;

    const size_t encRow = (size_t)b * Sn;

    if (t == 0) {
        int n = -1;
        for (int s = Sn - 1; s >= 0; --s) {
            nxt[s] = n;
            if (pmask[(encRow + s) * Ln] != 0) n = s;
        }
        nxt[Sn] = n;
    }
    float kvA[8], kvB[8];
#pragma unroll
    for (int j = 0; j < 8; ++j) {
        float2 kv = __ldg((const float2*)
            (g_keysV + ((size_t)b * Kn + kgbl + rb + j) * D + c0));
        kvA[j] = kv.x; kvB[j] = kv.y;
    }
    for (int i = t; i < KH * D; i += 256) h[0][i] = 0.f;
    for (int i = t; i < KH * 8; i += 256) { np_sh[0][i] = 0.125f; gd_sh[0][i] = 0.f; }
    __syncthreads();

    int s   = nxt[Sn];
    int p   = 0;    // h read buffer
    int par = 0;    // np/gd read buffer

    const ulonglong2* Upk2 = (const ulonglong2*)g_Upk;

    while (s >= 0) {
        const int snext = nxt[s];

        // ---- rs/gate for this step: redundant per warp (lanes lh==0) ----
        if (lh == 0) {
            float ssum = 0.f, gsum = 0.f;
#pragma unroll
            for (int q = 0; q < 8; ++q) {
                ssum += np_sh[par][ll * 8 + q];
                gsum += gd_sh[par][ll * 8 + q];
            }
            float rsv = rsqrtf(fmaxf(ssum, 1e-12f));
            float ek  = __ldg(g_eK + (encRow + s) * Kn + kgbl + ll);
            rs_sh[ll]   = rsv;
            gate_sh[ll] = 1.f / (1.f + expf(-(fmaf(rsv, gsum, ek))));
        }

        // ---- GEMM partial over own interleaved d-half ----
        const float* hb = h[p];
        unsigned long long accA[16], accB[16];
#pragma unroll
        for (int r = 0; r < 16; ++r) { accA[r] = 0ull; accB[r] = 0ull; }

#pragma unroll
        for (int g8 = 0; g8 < 8; ++g8) {
            const int p0 = g8 * 16 + lh * 8;   // interleaved d-split
            ulonglong2 u0 = __ldg(Upk2 + (size_t)(p0 + 0) * 128 + cp);
            ulonglong2 u1 = __ldg(Upk2 + (size_t)(p0 + 1) * 128 + cp);
            ulonglong2 u2 = __ldg(Upk2 + (size_t)(p0 + 2) * 128 + cp);
            ulonglong2 u3 = __ldg(Upk2 + (size_t)(p0 + 3) * 128 + cp);
            ulonglong2 u4 = __ldg(Upk2 + (size_t)(p0 + 4) * 128 + cp);
            ulonglong2 u5 = __ldg(Upk2 + (size_t)(p0 + 5) * 128 + cp);
            ulonglong2 u6 = __ldg(Upk2 + (size_t)(p0 + 6) * 128 + cp);
            ulonglong2 u7 = __ldg(Upk2 + (size_t)(p0 + 7) * 128 + cp);
#pragma unroll
            for (int r = 0; r < 16; ++r) {
                const ulonglong2* hp = (const ulonglong2*)&hb[r * D + p0 * 2];
                ulonglong2 h0 = hp[0], h1 = hp[1], h2 = hp[2], h3 = hp[3];
                FMA_F32X2(accA[r], h0.x, u0.x, accA[r]);
                FMA_F32X2(accB[r], h0.x, u0.y, accB[r]);
                FMA_F32X2(accA[r], h0.y, u1.x, accA[r]);
                FMA_F32X2(accB[r], h0.y, u1.y, accB[r]);
                FMA_F32X2(accA[r], h1.x, u2.x, accA[r]);
                FMA_F32X2(accB[r], h1.x, u2.y, accB[r]);
                FMA_F32X2(accA[r], h1.y, u3.x, accA[r]);
                FMA_F32X2(accB[r], h1.y, u3.y, accB[r]);
                FMA_F32X2(accA[r], h2.x, u4.x, accA[r]);
                FMA_F32X2(accB[r], h2.x, u4.y, accB[r]);
                FMA_F32X2(accA[r], h2.y, u5.x, accA[r]);
                FMA_F32X2(accB[r], h2.y, u5.y, accB[r]);
                FMA_F32X2(accA[r], h3.x, u6.x, accA[r]);
                FMA_F32X2(accB[r], h3.x, u6.y, accB[r]);
                FMA_F32X2(accA[r], h3.y, u7.x, accA[r]);
                FMA_F32X2(accB[r], h3.y, u7.y, accB[r]);
            }
        }

        // collapse + partner swap (keep own 8 rows, swap the other 8)
        float sA[16], sB[16];
#pragma unroll
        for (int r = 0; r < 16; ++r) {
            float2 aA = *(float2*)&accA[r];
            float2 aB = *(float2*)&accB[r];
            sA[r] = aA.x + aA.y;
            sB[r] = aB.x + aB.y;
        }
        float myA[8], myB[8];
#pragma unroll
        for (int j = 0; j < 8; ++j) {
            float keepA = lh ? sA[8 + j] : sA[j];
            float sendA = lh ? sA[j]     : sA[8 + j];
            float keepB = lh ? sB[8 + j] : sB[j];
            float sendB = lh ? sB[j]     : sB[8 + j];
            myA[j] = keepA + __shfl_xor_sync(0xffffffffu, sendA, 16);
            myB[j] = keepB + __shfl_xor_sync(0xffffffffu, sendB, 16);
        }

        // prefetch per-step scalars (hide under epilogue)
        const float2 ew = __ldg((const float2*)(g_encW + (encRow + s) * D + c0));
        float2 en = make_float2(0.f, 0.f);
        if (snext >= 0)
            en = __ldg((const float2*)(g_enc + (encRow + snext) * D + c0));

        __syncwarp();   // own warp's rs_sh/gate_sh writes visible

        // ---- epilogue: rows rb..rb+7 x 2 cols -> h[p^1] ----
        float* hw = h[p ^ 1];
        const int parw = par ^ 1;
        float np[8], gd[8];
#pragma unroll
        for (int j = 0; j < 8; ++j) {
            int   r  = rb + j;
            float rs = rs_sh[r];
            float gt = gate_sh[r];
            float2 hold = *(float2*)&hb[r * D + c0];
            float htA = fmaxf(fmaf(rs, myA[j], kvA[j] + ew.x), 0.f);
            float htB = fmaxf(fmaf(rs, myB[j], kvB[j] + ew.y), 0.f);
            float hA = fmaf(gt, htA, rs * hold.x);
            float hB = fmaf(gt, htB, rs * hold.y);
            *(float2*)&hw[r * D + c0] = make_float2(hA, hB);
            np[j] = fmaf(hA, hA, hB * hB);
            gd[j] = fmaf(en.x, hA, en.y * hB);
        }
#pragma unroll
        for (int o = 8; o > 0; o >>= 1) {
#pragma unroll
            for (int j = 0; j < 8; ++j) {
                np[j] += __shfl_xor_sync(0xffffffffu, np[j], o);
                gd[j] += __shfl_xor_sync(0xffffffffu, gd[j], o);
            }
        }
        if (ll == 0) {
#pragma unroll
            for (int j = 0; j < 8; ++j) {
                np_sh[parw][(rb + j) * 8 + w] = np[j];
                gd_sh[parw][(rb + j) * 8 + w] = gd[j];
            }
        }

        __syncthreads();   // single per-step barrier
        p ^= 1; par ^= 1;
        s = snext;
    }

    // final rs (redundant per warp, benign race; ordered by last barrier)
    if (lh == 0) {
        float ssum = 0.f;
#pragma unroll
        for (int q = 0; q < 8; ++q) ssum += np_sh[par][ll * 8 + q];
        rs_sh[ll] = rsqrtf(fmaxf(ssum, 1e-12f));
    }
    __syncwarp();
#pragma unroll
    for (int j = 0; j < 8; ++j) {
        int r = rb + j;
        float2 hv = *(float2*)&h[p][r * D + c0];
        *(float2*)&out[((size_t)b * Kn + kgbl + r) * D + c0] =
            make_float2(hv.x * rs_sh[r], hv.y * rs_sh[r]);
    }
}

// ---------------------------------------------------------------------------
extern "C" void kernel_launch(void* const* d_in, const int* in_sizes, int n_in,
                              void* d_out, int out_size) {
    const int*   prgrph = (const int*)d_in[0];
    const int*   pmask  = (const int*)d_in[1];
    const float* keys   = (const float*)d_in[2];
    const float* emb    = (const float*)d_in[3];
    const float* U      = (const float*)d_in[4];
    const float* V      = (const float*)d_in[5];
    const float* W      = (const float*)d_in[6];
    float*       out    = (float*)d_out;

    pack_kernel<<<384, 256>>>(U, W, V);
    gather_eK_kernel<<<Bn * Sn, 256>>>(prgrph, emb, keys);
    gemm_pre_kernel<<<768, 256>>>(keys);
    scan_kernel<<<Bn * 2, 256>>>(pmask, out);
}